// round 2
// baseline (speedup 1.0000x reference)
#include <cuda_runtime.h>
#include <cuda_bf16.h>
#include <math.h>

// ---------------- scratch (device globals; no allocations) ----------------
__device__ float g_bufA[4u * 256u * 64u * 64u];   // 4.19M floats
__device__ float g_bufB[4u * 256u * 64u * 64u];   // 4.19M floats
__device__ float g_warp[4 * 2 * 64 * 64];
__device__ float g_stats[1024];                   // [mean(C) | rsqrt(var+eps)(C)]

// ---------------------------------------------------------------------------
// Kernel 1: fused correlation + softmax + expected grid position
// corr[b,j,p] = dot64(f0[b,:,p], f1[b,:,j]) / 8 ; P = softmax_j ;
// warp[b,0,p] = sum_j P*gx(j), warp[b,1,p] = sum_j P*gy(j)
// block: 128 threads, 32 pixels; loops j in tiles of 128 (online softmax)
// ---------------------------------------------------------------------------
__global__ __launch_bounds__(128) void corr_kernel(
    const float* __restrict__ f0, const float* __restrict__ f1,
    float* __restrict__ warp)
{
    const int b  = blockIdx.x >> 7;          // 128 pixel-blocks per batch
    const int p0 = (blockIdx.x & 127) * 32;

    __shared__ float f0_s[64][32];
    __shared__ float f1_sc[64 * 128];        // f1 tile, reused as score buffer
    __shared__ float m_s[32], l_s[32], sx_s[32], sy_s[32];

    const int t    = threadIdx.x;
    const int tx   = t & 15;                 // j-group  (16 x 8 j)
    const int ty   = t >> 4;                 // p-group  (8  x 4 p)
    const int q    = t >> 2;                 // softmax pixel owner group
    const int quad = t & 3;

    // load f0 tile: 64c x 32p
    for (int i = t; i < 64 * 32; i += 128) {
        int p = i & 31, c = i >> 5;
        f0_s[c][p] = f0[(b * 64 + c) * 4096 + p0 + p];
    }
    if (t < 32) { m_s[t] = -1e30f; l_s[t] = 0.f; sx_s[t] = 0.f; sy_s[t] = 0.f; }
    __syncthreads();

    for (int j0 = 0; j0 < 4096; j0 += 128) {
        // load f1 tile: 64c x 128j
        for (int i = t; i < 64 * 128; i += 128) {
            int j = i & 127, c = i >> 7;
            f1_sc[c * 128 + j] = f1[(b * 64 + c) * 4096 + j0 + j];
        }
        __syncthreads();

        float acc[4][8];
        #pragma unroll
        for (int i = 0; i < 4; i++)
            #pragma unroll
            for (int jj = 0; jj < 8; jj++) acc[i][jj] = 0.f;

        #pragma unroll 16
        for (int c = 0; c < 64; c++) {
            float4 a0 = *(const float4*)&f0_s[c][ty * 4];
            float4 b0 = *(const float4*)&f1_sc[c * 128 + tx * 8];
            float4 b1 = *(const float4*)&f1_sc[c * 128 + tx * 8 + 4];
            float av[4] = {a0.x, a0.y, a0.z, a0.w};
            float bv[8] = {b0.x, b0.y, b0.z, b0.w, b1.x, b1.y, b1.z, b1.w};
            #pragma unroll
            for (int i = 0; i < 4; i++)
                #pragma unroll
                for (int jj = 0; jj < 8; jj++)
                    acc[i][jj] = fmaf(av[i], bv[jj], acc[i][jj]);
        }
        __syncthreads();   // done reading f1 tile; now reuse as score buffer

        // write scores: sc[pixel][j] with row stride 132 (== 4 mod 32)
        #pragma unroll
        for (int i = 0; i < 4; i++)
            #pragma unroll
            for (int jj = 0; jj < 8; jj++)
                f1_sc[(ty * 4 + i) * 132 + tx * 8 + jj] = acc[i][jj] * 0.125f;
        __syncthreads();

        // online softmax: 4 threads per pixel, each handles 32 strided j's
        float m_old = m_s[q];
        float sc[32];
        float tm = -1e30f;
        #pragma unroll
        for (int i = 0; i < 32; i++) {
            sc[i] = f1_sc[q * 132 + quad + 4 * i];   // bank = 4q+quad+4i: conflict-free
            tm = fmaxf(tm, sc[i]);
        }
        tm = fmaxf(tm, __shfl_xor_sync(0xffffffffu, tm, 1));
        tm = fmaxf(tm, __shfl_xor_sync(0xffffffffu, tm, 2));
        float nm = fmaxf(m_old, tm);

        float le = 0.f, lx = 0.f, ly = 0.f;
        #pragma unroll
        for (int i = 0; i < 32; i++) {
            int j   = j0 + quad + 4 * i;
            float e = __expf(sc[i] - nm);
            float gx = (float)((j & 63) * 2 + 1) * (1.f / 64.f) - 1.f;
            float gy = (float)((j >> 6) * 2 + 1) * (1.f / 64.f) - 1.f;
            le += e;
            lx = fmaf(e, gx, lx);
            ly = fmaf(e, gy, ly);
        }
        le += __shfl_xor_sync(0xffffffffu, le, 1);
        le += __shfl_xor_sync(0xffffffffu, le, 2);
        lx += __shfl_xor_sync(0xffffffffu, lx, 1);
        lx += __shfl_xor_sync(0xffffffffu, lx, 2);
        ly += __shfl_xor_sync(0xffffffffu, ly, 1);
        ly += __shfl_xor_sync(0xffffffffu, ly, 2);

        if (quad == 0) {
            float s = __expf(m_old - nm);
            l_s[q]  = l_s[q]  * s + le;
            sx_s[q] = sx_s[q] * s + lx;
            sy_s[q] = sy_s[q] * s + ly;
            m_s[q]  = nm;
        }
        __syncthreads();
    }

    if (t < 32) {
        float inv = 1.f / l_s[t];
        warp[(b * 2 + 0) * 4096 + p0 + t] = sx_s[t] * inv;
        warp[(b * 2 + 1) * 4096 + p0 + t] = sy_s[t] * inv;
    }
}

// ---------------------------------------------------------------------------
// Kernel 2: direct conv3x3, SAME, fp32.  grid(W/64, H/4, B*Cout/32), 256 thr.
// Each thread: 8 co x 4 h at one w. Cin chunked by 8 (zero-padded tail).
// ---------------------------------------------------------------------------
__global__ __launch_bounds__(256) void conv3x3_kernel(
    const float* __restrict__ in, const float* __restrict__ wgt,
    float* __restrict__ out, int B_, int Cin, int Cout, int H, int W)
{
    const int w0 = blockIdx.x * 64;
    const int h0 = blockIdx.y * 4;
    const int coBlocks = Cout >> 5;
    const int b   = blockIdx.z / coBlocks;
    const int cob = (blockIdx.z % coBlocks) * 32;

    __shared__ float in_s[8][6][66];
    __shared__ float w_s[32][8][9];

    const int t   = threadIdx.x;
    const int wl  = t & 63;
    const int grp = t >> 6;   // 0..3 -> co sub-group of 8

    float acc[8][4];
    #pragma unroll
    for (int i = 0; i < 8; i++)
        #pragma unroll
        for (int hh = 0; hh < 4; hh++) acc[i][hh] = 0.f;

    for (int ci0 = 0; ci0 < Cin; ci0 += 8) {
        // input tile 8 x 6 x 66 (with halo, zero-padded)
        for (int i = t; i < 8 * 6 * 66; i += 256) {
            int ww = i % 66; int rem = i / 66; int hh = rem % 6; int ci = rem / 6;
            int gh = h0 + hh - 1, gw = w0 + ww - 1, gc = ci0 + ci;
            float v = 0.f;
            if (gc < Cin && (unsigned)gh < (unsigned)H && (unsigned)gw < (unsigned)W)
                v = in[((b * Cin + gc) * H + gh) * W + gw];
            in_s[ci][hh][ww] = v;
        }
        // weights 32 x 8 x 9
        for (int i = t; i < 32 * 8 * 9; i += 256) {
            int k = i % 9; int rem = i / 9; int ci = rem % 8; int co = rem / 8;
            int gc = ci0 + ci;
            w_s[co][ci][k] = (gc < Cin) ? wgt[((cob + co) * Cin + gc) * 9 + k] : 0.f;
        }
        __syncthreads();

        #pragma unroll
        for (int ci = 0; ci < 8; ci++) {
            #pragma unroll
            for (int kh = 0; kh < 3; kh++) {
                #pragma unroll
                for (int kw = 0; kw < 3; kw++) {
                    float iv[4];
                    #pragma unroll
                    for (int hh = 0; hh < 4; hh++) iv[hh] = in_s[ci][hh + kh][wl + kw];
                    #pragma unroll
                    for (int i = 0; i < 8; i++) {
                        float wv = w_s[grp * 8 + i][ci][kh * 3 + kw];
                        #pragma unroll
                        for (int hh = 0; hh < 4; hh++)
                            acc[i][hh] = fmaf(wv, iv[hh], acc[i][hh]);
                    }
                }
            }
        }
        __syncthreads();
    }

    #pragma unroll
    for (int i = 0; i < 8; i++)
        #pragma unroll
        for (int hh = 0; hh < 4; hh++)
            out[((b * Cout + cob + grp * 8 + i) * H + h0 + hh) * W + w0 + wl] = acc[i][hh];
}

// ---------------------------------------------------------------------------
// BN stats: one block per channel; mean & rsqrt(var+eps) over (B,H,W)
// ---------------------------------------------------------------------------
__global__ __launch_bounds__(256) void bnstats_kernel(
    const float* __restrict__ x, float* __restrict__ stats,
    int B_, int C, int HW)
{
    const int c = blockIdx.x;
    const int N = B_ * HW;
    float s = 0.f, sq = 0.f;
    for (int i = threadIdx.x; i < N; i += 256) {
        int b = i / HW, p = i - b * HW;
        float v = x[(b * C + c) * HW + p];
        s += v; sq = fmaf(v, v, sq);
    }
    __shared__ float rs[256], rq[256];
    rs[threadIdx.x] = s; rq[threadIdx.x] = sq;
    __syncthreads();
    for (int off = 128; off > 0; off >>= 1) {
        if (threadIdx.x < off) {
            rs[threadIdx.x] += rs[threadIdx.x + off];
            rq[threadIdx.x] += rq[threadIdx.x + off];
        }
        __syncthreads();
    }
    if (threadIdx.x == 0) {
        float m   = rs[0] / (float)N;
        float var = rq[0] / (float)N - m * m;
        stats[c]     = m;
        stats[C + c] = rsqrtf(var + 1e-5f);
    }
}

__global__ void bnrelu_kernel(float* __restrict__ x, const float* __restrict__ stats,
                              int C, int HW, int total)
{
    int i = blockIdx.x * blockDim.x + threadIdx.x;
    if (i >= total) return;
    int c = (i / HW) % C;
    float v = (x[i] - stats[c]) * stats[C + c];
    x[i] = v > 0.f ? v : 0.f;
}

// ---------------------------------------------------------------------------
// grid_sample (zero padding, bilinear), writes into concat buffer at dstCoff
// coords: gx at coords[b*cStrideB + p], gy at coords[b*cStrideB + gyOff + p]
// ---------------------------------------------------------------------------
__global__ void gridsample_kernel(
    const float* __restrict__ img, const float* __restrict__ coords,
    float* __restrict__ dst, int B_, int C, int H, int W,
    int cStrideB, int gyOff, int dstCtot, int dstCoff)
{
    int idx = blockIdx.x * blockDim.x + threadIdx.x;
    int HW = H * W;
    if (idx >= B_ * C * HW) return;
    int p = idx % HW;
    int c = (idx / HW) % C;
    int b = idx / (HW * C);

    float gx = coords[b * cStrideB + p];
    float gy = coords[b * cStrideB + gyOff + p];
    float x = (gx + 1.f) * (W * 0.5f) - 0.5f;
    float y = (gy + 1.f) * (H * 0.5f) - 0.5f;
    float x0f = floorf(x), y0f = floorf(y);
    float wx = x - x0f, wy = y - y0f;
    int x0 = (int)x0f, y0 = (int)y0f;

    const float* ip = img + (b * C + c) * HW;
    auto samp = [&](int yi, int xi) -> float {
        bool valid = (xi >= 0) && (xi < W) && (yi >= 0) && (yi < H);
        int yc = min(max(yi, 0), H - 1);
        int xc = min(max(xi, 0), W - 1);
        return valid ? ip[yc * W + xc] : 0.f;
    };
    float r = samp(y0,     x0    ) * (1.f - wx) * (1.f - wy)
            + samp(y0,     x0 + 1) * wx         * (1.f - wy)
            + samp(y0 + 1, x0    ) * (1.f - wx) * wy
            + samp(y0 + 1, x0 + 1) * wx         * wy;
    dst[((b * dstCtot) + dstCoff + c) * HW + p] = r;
}

// ---------------------------------------------------------------------------
// strided per-batch copy (for concat assembly)
// ---------------------------------------------------------------------------
__global__ void copy_strided_kernel(const float* __restrict__ src, float* __restrict__ dst,
                                    int perB, int srcStride, int dstStride, int B_)
{
    int i = blockIdx.x * blockDim.x + threadIdx.x;
    if (i >= B_ * perB) return;
    int b = i / perB, r = i - b * perB;
    dst[b * dstStride + r] = src[b * srcStride + r];
}

// ---------------------------------------------------------------------------
// bilinear 2x upsample (jax.image.resize 'bilinear': half-pixel + edge clamp)
// ---------------------------------------------------------------------------
__global__ void upsample2x_kernel(const float* __restrict__ src, float* __restrict__ dst,
                                  int B_, int C, int Hi, int Wi)
{
    int Ho = Hi * 2, Wo = Wi * 2;
    int idx = blockIdx.x * blockDim.x + threadIdx.x;
    if (idx >= B_ * C * Ho * Wo) return;
    int wo = idx % Wo;
    int ho = (idx / Wo) % Ho;
    int bc = idx / (Wo * Ho);

    float sy = ho * 0.5f - 0.25f;
    float sx = wo * 0.5f - 0.25f;
    float fy = sy - floorf(sy);
    float fx = sx - floorf(sx);
    int y0 = (int)floorf(sy), x0 = (int)floorf(sx);
    int y0c = min(max(y0, 0), Hi - 1), y1c = min(max(y0 + 1, 0), Hi - 1);
    int x0c = min(max(x0, 0), Wi - 1), x1c = min(max(x0 + 1, 0), Wi - 1);

    const float* sp = src + bc * Hi * Wi;
    float v = sp[y0c * Wi + x0c] * (1.f - fy) * (1.f - fx)
            + sp[y0c * Wi + x1c] * (1.f - fy) * fx
            + sp[y1c * Wi + x0c] * fy * (1.f - fx)
            + sp[y1c * Wi + x1c] * fy * fx;
    dst[idx] = v;
}

// ---------------------------------------------------------------------------
// 1x1 conv to 3 channels + bias + base add  (base can be 2ch [warp + 0] or 3ch)
// ---------------------------------------------------------------------------
__global__ void conv1x1_3_kernel(
    const float* __restrict__ x, const float* __restrict__ w5, const float* __restrict__ b5,
    const float* __restrict__ base, int baseC, int baseStrideB,
    float* __restrict__ out, int Cin, int HW, int B_)
{
    int idx = blockIdx.x * blockDim.x + threadIdx.x;
    if (idx >= B_ * HW) return;
    int b = idx / HW, p = idx - b * HW;

    float a0 = 0.f, a1 = 0.f, a2 = 0.f;
    const float* xp = x + (size_t)b * Cin * HW + p;
    for (int ci = 0; ci < Cin; ci++) {
        float v = xp[(size_t)ci * HW];
        a0 = fmaf(v, __ldg(&w5[ci]),            a0);
        a1 = fmaf(v, __ldg(&w5[Cin + ci]),      a1);
        a2 = fmaf(v, __ldg(&w5[2 * Cin + ci]),  a2);
    }
    float b0v = base[b * baseStrideB + p];
    float b1v = base[b * baseStrideB + HW + p];
    float b2v = (baseC > 2) ? base[b * baseStrideB + 2 * HW + p] : 0.f;

    out[(size_t)b * 3 * HW + p]           = a0 + __ldg(&b5[0]) + b0v;
    out[(size_t)b * 3 * HW + HW + p]      = a1 + __ldg(&b5[1]) + b1v;
    out[(size_t)b * 3 * HW + 2 * HW + p]  = a2 + __ldg(&b5[2]) + b2v;
}

// ---------------------------------------------------------------------------
extern "C" void kernel_launch(void* const* d_in, const int* in_sizes, int n_in,
                              void* d_out, int out_size)
{
    const float* f0c = (const float*)d_in[0];
    const float* f1c = (const float*)d_in[1];
    const float* f0f = (const float*)d_in[2];
    const float* f1f = (const float*)d_in[3];
    const float* cw1 = (const float*)d_in[4];
    const float* cw2 = (const float*)d_in[5];
    const float* cw3 = (const float*)d_in[6];
    const float* cw4 = (const float*)d_in[7];
    const float* cw5 = (const float*)d_in[8];
    const float* cb5 = (const float*)d_in[9];
    const float* fw1 = (const float*)d_in[10];
    const float* fw2 = (const float*)d_in[11];
    const float* fw3 = (const float*)d_in[12];
    const float* fw4 = (const float*)d_in[13];
    const float* fw5 = (const float*)d_in[14];
    const float* fb5 = (const float*)d_in[15];

    float *A, *Bb, *warp, *stats;
    cudaGetSymbolAddress((void**)&A,     g_bufA);
    cudaGetSymbolAddress((void**)&Bb,    g_bufB);
    cudaGetSymbolAddress((void**)&warp,  g_warp);
    cudaGetSymbolAddress((void**)&stats, g_stats);

    float* outC = (float*)d_out;                 // (4,3,64,64)
    float* outF = outC + 4 * 3 * 64 * 64;        // (4,3,128,128)

    const int HWc = 64 * 64, HWf = 128 * 128;

    // ---- coarse stage ----
    corr_kernel<<<512, 128>>>(f0c, f1c, warp);

    copy_strided_kernel<<<(4 * 64 * HWc + 255) / 256, 256>>>(
        f0c, A, 64 * HWc, 64 * HWc, 130 * HWc, 4);
    copy_strided_kernel<<<(4 * 2 * HWc + 255) / 256, 256>>>(
        warp, A + 128 * HWc, 2 * HWc, 2 * HWc, 130 * HWc, 4);
    gridsample_kernel<<<(4 * 64 * HWc + 255) / 256, 256>>>(
        f1c, warp, A, 4, 64, 64, 64, 2 * HWc, HWc, 130, 64);

    dim3 cg(1, 16, 32);   // W/64=1, H/4=16, B*Cout/32=32
    conv3x3_kernel<<<cg, 256>>>(A, cw1, Bb, 4, 130, 256, 64, 64);
    bnstats_kernel<<<256, 256>>>(Bb, stats, 4, 256, HWc);
    bnrelu_kernel<<<(4 * 256 * HWc + 255) / 256, 256>>>(Bb, stats, 256, HWc, 4 * 256 * HWc);

    conv3x3_kernel<<<cg, 256>>>(Bb, cw2, A, 4, 256, 256, 64, 64);
    bnstats_kernel<<<256, 256>>>(A, stats, 4, 256, HWc);
    bnrelu_kernel<<<(4 * 256 * HWc + 255) / 256, 256>>>(A, stats, 256, HWc, 4 * 256 * HWc);

    conv3x3_kernel<<<cg, 256>>>(A, cw3, Bb, 4, 256, 256, 64, 64);
    bnstats_kernel<<<256, 256>>>(Bb, stats, 4, 256, HWc);
    bnrelu_kernel<<<(4 * 256 * HWc + 255) / 256, 256>>>(Bb, stats, 256, HWc, 4 * 256 * HWc);

    conv3x3_kernel<<<cg, 256>>>(Bb, cw4, A, 4, 256, 256, 64, 64);
    bnstats_kernel<<<256, 256>>>(A, stats, 4, 256, HWc);
    bnrelu_kernel<<<(4 * 256 * HWc + 255) / 256, 256>>>(A, stats, 256, HWc, 4 * 256 * HWc);

    conv1x1_3_kernel<<<(4 * HWc + 127) / 128, 128>>>(
        A, cw5, cb5, warp, 2, 2 * HWc, outC, 256, HWc, 4);

    // ---- fine stage ----
    upsample2x_kernel<<<(4 * 3 * HWf + 255) / 256, 256>>>(outC, outF, 4, 3, 64, 64);

    copy_strided_kernel<<<(4 * 24 * HWf + 255) / 256, 256>>>(
        f0f, Bb, 24 * HWf, 24 * HWf, 50 * HWf, 4);
    copy_strided_kernel<<<(4 * 2 * HWf + 255) / 256, 256>>>(
        outF, Bb + 48 * HWf, 2 * HWf, 3 * HWf, 50 * HWf, 4);
    gridsample_kernel<<<(4 * 24 * HWf + 255) / 256, 256>>>(
        f1f, outF, Bb, 4, 24, 128, 128, 3 * HWf, HWf, 50, 24);

    dim3 fg(2, 32, 8);    // W/64=2, H/4=32, B*Cout/32=8
    conv3x3_kernel<<<fg, 256>>>(Bb, fw1, A, 4, 50, 64, 128, 128);
    bnstats_kernel<<<64, 256>>>(A, stats, 4, 64, HWf);
    bnrelu_kernel<<<(4 * 64 * HWf + 255) / 256, 256>>>(A, stats, 64, HWf, 4 * 64 * HWf);

    conv3x3_kernel<<<fg, 256>>>(A, fw2, Bb, 4, 64, 64, 128, 128);
    bnstats_kernel<<<64, 256>>>(Bb, stats, 4, 64, HWf);
    bnrelu_kernel<<<(4 * 64 * HWf + 255) / 256, 256>>>(Bb, stats, 64, HWf, 4 * 64 * HWf);

    conv3x3_kernel<<<fg, 256>>>(Bb, fw3, A, 4, 64, 64, 128, 128);
    bnstats_kernel<<<64, 256>>>(A, stats, 4, 64, HWf);
    bnrelu_kernel<<<(4 * 64 * HWf + 255) / 256, 256>>>(A, stats, 64, HWf, 4 * 64 * HWf);

    conv3x3_kernel<<<fg, 256>>>(A, fw4, Bb, 4, 64, 64, 128, 128);
    bnstats_kernel<<<64, 256>>>(Bb, stats, 4, 64, HWf);
    bnrelu_kernel<<<(4 * 64 * HWf + 255) / 256, 256>>>(Bb, stats, 64, HWf, 4 * 64 * HWf);

    conv1x1_3_kernel<<<(4 * HWf + 127) / 128, 128>>>(
        Bb, fw5, fb5, outF, 3, 3 * HWf, outF, 64, HWf, 4);
}

// round 4
// speedup vs baseline: 1.0209x; 1.0209x over previous
#include <cuda_runtime.h>
#include <cuda_bf16.h>
#include <math.h>

typedef unsigned long long u64;

__device__ __forceinline__ u64 pack2(float lo, float hi) {
    u64 r; asm("mov.b64 %0,{%1,%2};" : "=l"(r) : "f"(lo), "f"(hi)); return r;
}
__device__ __forceinline__ void unpack2(u64 v, float& lo, float& hi) {
    asm("mov.b64 {%0,%1},%2;" : "=f"(lo), "=f"(hi) : "l"(v));
}
__device__ __forceinline__ u64 fma2(u64 a, u64 b, u64 c) {
    u64 d; asm("fma.rn.f32x2 %0,%1,%2,%3;" : "=l"(d) : "l"(a), "l"(b), "l"(c)); return d;
}

// ---------------- scratch (device globals; no allocations) ----------------
__device__ float g_bufA[4u * 256u * 64u * 64u];
__device__ float g_bufB[4u * 256u * 64u * 64u];
__device__ float g_warp[4 * 2 * 64 * 64];
__device__ float g_stats[1024];                   // [mean(C) | rsqrt(var+eps)(C)]

// ---------------------------------------------------------------------------
// Kernel 1: fused correlation + softmax + expected grid position (f32x2 GEMM)
// ---------------------------------------------------------------------------
__global__ __launch_bounds__(128) void corr_kernel(
    const float* __restrict__ f0, const float* __restrict__ f1,
    float* __restrict__ warp)
{
    const int b  = blockIdx.x >> 7;
    const int p0 = (blockIdx.x & 127) * 32;

    __shared__ __align__(16) float f0_s[64][32];
    __shared__ __align__(16) float f1_sc[64 * 128];   // f1 tile / score buffer
    __shared__ float m_s[32], l_s[32], sx_s[32], sy_s[32];

    const int t    = threadIdx.x;
    const int tx   = t & 15;
    const int ty   = t >> 4;
    const int q    = t >> 2;
    const int quad = t & 3;

    for (int i = t; i < 64 * 32; i += 128) {
        int p = i & 31, c = i >> 5;
        f0_s[c][p] = f0[(b * 64 + c) * 4096 + p0 + p];
    }
    if (t < 32) { m_s[t] = -1e30f; l_s[t] = 0.f; sx_s[t] = 0.f; sy_s[t] = 0.f; }
    __syncthreads();

    for (int j0 = 0; j0 < 4096; j0 += 128) {
        for (int i = t; i < 64 * 128; i += 128) {
            int j = i & 127, c = i >> 7;
            f1_sc[c * 128 + j] = f1[(b * 64 + c) * 4096 + j0 + j];
        }
        __syncthreads();

        u64 acc2[4][4];
        #pragma unroll
        for (int i = 0; i < 4; i++)
            #pragma unroll
            for (int jp = 0; jp < 4; jp++) acc2[i][jp] = 0ull;

        #pragma unroll 16
        for (int c = 0; c < 64; c++) {
            float4 a0 = *(const float4*)&f0_s[c][ty * 4];
            u64 ap[4] = { pack2(a0.x, a0.x), pack2(a0.y, a0.y),
                          pack2(a0.z, a0.z), pack2(a0.w, a0.w) };
            const u64* bp = (const u64*)&f1_sc[c * 128 + tx * 8];
            u64 b0 = bp[0], b1 = bp[1], b2 = bp[2], b3 = bp[3];
            #pragma unroll
            for (int i = 0; i < 4; i++) {
                acc2[i][0] = fma2(ap[i], b0, acc2[i][0]);
                acc2[i][1] = fma2(ap[i], b1, acc2[i][1]);
                acc2[i][2] = fma2(ap[i], b2, acc2[i][2]);
                acc2[i][3] = fma2(ap[i], b3, acc2[i][3]);
            }
        }
        __syncthreads();   // done reading f1 tile; reuse as score buffer

        #pragma unroll
        for (int i = 0; i < 4; i++)
            #pragma unroll
            for (int jp = 0; jp < 4; jp++) {
                float lo, hi; unpack2(acc2[i][jp], lo, hi);
                f1_sc[(ty * 4 + i) * 132 + tx * 8 + 2 * jp]     = lo * 0.125f;
                f1_sc[(ty * 4 + i) * 132 + tx * 8 + 2 * jp + 1] = hi * 0.125f;
            }
        __syncthreads();

        float m_old = m_s[q];
        float sc[32];
        float tm = -1e30f;
        #pragma unroll
        for (int i = 0; i < 32; i++) {
            sc[i] = f1_sc[q * 132 + quad + 4 * i];
            tm = fmaxf(tm, sc[i]);
        }
        tm = fmaxf(tm, __shfl_xor_sync(0xffffffffu, tm, 1));
        tm = fmaxf(tm, __shfl_xor_sync(0xffffffffu, tm, 2));
        float nm = fmaxf(m_old, tm);

        float le = 0.f, lx = 0.f, ly = 0.f;
        #pragma unroll
        for (int i = 0; i < 32; i++) {
            int j   = j0 + quad + 4 * i;
            float e = __expf(sc[i] - nm);
            float gx = (float)((j & 63) * 2 + 1) * (1.f / 64.f) - 1.f;
            float gy = (float)((j >> 6) * 2 + 1) * (1.f / 64.f) - 1.f;
            le += e;
            lx = fmaf(e, gx, lx);
            ly = fmaf(e, gy, ly);
        }
        le += __shfl_xor_sync(0xffffffffu, le, 1);
        le += __shfl_xor_sync(0xffffffffu, le, 2);
        lx += __shfl_xor_sync(0xffffffffu, lx, 1);
        lx += __shfl_xor_sync(0xffffffffu, lx, 2);
        ly += __shfl_xor_sync(0xffffffffu, ly, 1);
        ly += __shfl_xor_sync(0xffffffffu, ly, 2);

        if (quad == 0) {
            float s = __expf(m_old - nm);
            l_s[q]  = l_s[q]  * s + le;
            sx_s[q] = sx_s[q] * s + lx;
            sy_s[q] = sy_s[q] * s + ly;
            m_s[q]  = nm;
        }
        __syncthreads();
    }

    if (t < 32) {
        float inv = 1.f / l_s[t];
        warp[(b * 2 + 0) * 4096 + p0 + t] = sx_s[t] * inv;
        warp[(b * 2 + 1) * 4096 + p0 + t] = sy_s[t] * inv;
    }
}

// ---------------------------------------------------------------------------
// Kernel 2: direct conv3x3, SAME, fp32 via f32x2. Optional BN+ReLU fold on
// the INPUT (bn = [mean(Cin) | rstd(Cin)] or nullptr).
// grid(W/64, H/4, B*Cout/32), 256 thr. Thread: 8 co (4 pairs) x 4 h x 1 w.
// Register double-buffered gmem->smem chunk loads (ci chunk = 8).
// ---------------------------------------------------------------------------
__global__ __launch_bounds__(256) void conv3x3_kernel(
    const float* __restrict__ in, const float* __restrict__ wgt,
    const float* __restrict__ bn,
    float* __restrict__ out, int B_, int Cin, int Cout, int H, int W)
{
    const int w0 = blockIdx.x * 64;
    const int h0 = blockIdx.y * 4;
    const int coBlocks = Cout >> 5;
    const int b   = blockIdx.z / coBlocks;
    const int cob = (blockIdx.z % coBlocks) * 32;

    __shared__ __align__(16) float in_s[8][6][66];
    __shared__ __align__(16) float w_s[8][9][32];    // [ci][k][co] : co contiguous

    const int t   = threadIdx.x;
    const int wl  = t & 63;
    const int grp = t >> 6;
    const bool hasBN = (bn != nullptr);

    u64 acc2[4][4];
    #pragma unroll
    for (int cp = 0; cp < 4; cp++)
        #pragma unroll
        for (int hh = 0; hh < 4; hh++) acc2[cp][hh] = 0ull;

    float rin[13];
    float rw[9];

    auto load_regs = [&](int ci0) {
        #pragma unroll
        for (int k = 0; k < 13; k++) {
            int i = t + k * 256;
            float v = 0.f;
            if (i < 3168) {
                int ww = i % 66; int rem = i / 66; int hh = rem % 6; int ci = rem / 6;
                int gh = h0 + hh - 1, gw = w0 + ww - 1, gc = ci0 + ci;
                if (gc < Cin && (unsigned)gh < (unsigned)H && (unsigned)gw < (unsigned)W) {
                    v = in[((b * Cin + gc) * H + gh) * W + gw];
                    if (hasBN) v = fmaxf((v - bn[gc]) * bn[Cin + gc], 0.f);
                }
            }
            rin[k] = v;
        }
        #pragma unroll
        for (int k = 0; k < 9; k++) {
            int i = t + k * 256;
            int co = i & 31; int kk = (i >> 5) % 9; int ci = i / 288;
            int gc = ci0 + ci;
            rw[k] = (gc < Cin) ? wgt[((cob + co) * Cin + gc) * 9 + kk] : 0.f;
        }
    };

    auto store_regs = [&]() {
        #pragma unroll
        for (int k = 0; k < 13; k++) {
            int i = t + k * 256;
            if (i < 3168) {
                int ww = i % 66; int rem = i / 66; int hh = rem % 6; int ci = rem / 6;
                in_s[ci][hh][ww] = rin[k];
            }
        }
        #pragma unroll
        for (int k = 0; k < 9; k++) {
            int i = t + k * 256;
            int co = i & 31; int kk = (i >> 5) % 9; int ci = i / 288;
            w_s[ci][kk][co] = rw[k];
        }
    };

    const int nChunks = (Cin + 7) >> 3;
    load_regs(0);

    for (int c = 0; c < nChunks; c++) {
        __syncthreads();
        store_regs();
        __syncthreads();
        if (c + 1 < nChunks) load_regs((c + 1) * 8);

        #pragma unroll 2
        for (int ci = 0; ci < 8; ci++) {
            #pragma unroll
            for (int kw = 0; kw < 3; kw++) {
                u64 ivp[6];
                #pragma unroll
                for (int r = 0; r < 6; r++) {
                    float v = in_s[ci][r][wl + kw];
                    ivp[r] = pack2(v, v);
                }
                #pragma unroll
                for (int kh = 0; kh < 3; kh++) {
                    #pragma unroll
                    for (int cp = 0; cp < 4; cp++) {
                        u64 wp = *(const u64*)&w_s[ci][kh * 3 + kw][grp * 8 + cp * 2];
                        #pragma unroll
                        for (int hh = 0; hh < 4; hh++)
                            acc2[cp][hh] = fma2(wp, ivp[hh + kh], acc2[cp][hh]);
                    }
                }
            }
        }
    }

    #pragma unroll
    for (int cp = 0; cp < 4; cp++)
        #pragma unroll
        for (int hh = 0; hh < 4; hh++) {
            float lo, hi; unpack2(acc2[cp][hh], lo, hi);
            int co = cob + grp * 8 + cp * 2;
            out[((b * Cout + co)     * H + h0 + hh) * W + w0 + wl] = lo;
            out[((b * Cout + co + 1) * H + h0 + hh) * W + w0 + wl] = hi;
        }
}

// ---------------------------------------------------------------------------
// BN stats: one block per channel; mean & rsqrt(var+eps) over (B,H,W)
// ---------------------------------------------------------------------------
__global__ __launch_bounds__(512) void bnstats_kernel(
    const float* __restrict__ x, float* __restrict__ stats,
    int B_, int C, int HW)
{
    const int c = blockIdx.x;
    const int N = B_ * HW;
    float s = 0.f, sq = 0.f;
    for (int i = threadIdx.x; i < N; i += 512) {
        int b = i / HW, p = i - b * HW;
        float v = x[(b * C + c) * HW + p];
        s += v; sq = fmaf(v, v, sq);
    }
    __shared__ float rs[512], rq[512];
    rs[threadIdx.x] = s; rq[threadIdx.x] = sq;
    __syncthreads();
    for (int off = 256; off > 0; off >>= 1) {
        if (threadIdx.x < off) {
            rs[threadIdx.x] += rs[threadIdx.x + off];
            rq[threadIdx.x] += rq[threadIdx.x + off];
        }
        __syncthreads();
    }
    if (threadIdx.x == 0) {
        float m   = rs[0] / (float)N;
        float var = rq[0] / (float)N - m * m;
        stats[c]     = m;
        stats[C + c] = rsqrtf(var + 1e-5f);
    }
}

__global__ void bnrelu_kernel(float* __restrict__ x, const float* __restrict__ stats,
                              int C, int HW, int total)
{
    int i = blockIdx.x * blockDim.x + threadIdx.x;
    if (i >= total) return;
    int c = (i / HW) % C;
    float v = (x[i] - stats[c]) * stats[C + c];
    x[i] = v > 0.f ? v : 0.f;
}

// ---------------------------------------------------------------------------
// grid_sample (zero padding, bilinear), writes into concat buffer at dstCoff
// ---------------------------------------------------------------------------
__global__ void gridsample_kernel(
    const float* __restrict__ img, const float* __restrict__ coords,
    float* __restrict__ dst, int B_, int C, int H, int W,
    int cStrideB, int gyOff, int dstCtot, int dstCoff)
{
    int idx = blockIdx.x * blockDim.x + threadIdx.x;
    int HW = H * W;
    if (idx >= B_ * C * HW) return;
    int p = idx % HW;
    int c = (idx / HW) % C;
    int b = idx / (HW * C);

    float gx = coords[b * cStrideB + p];
    float gy = coords[b * cStrideB + gyOff + p];
    float x = (gx + 1.f) * (W * 0.5f) - 0.5f;
    float y = (gy + 1.f) * (H * 0.5f) - 0.5f;
    float x0f = floorf(x), y0f = floorf(y);
    float wx = x - x0f, wy = y - y0f;
    int x0 = (int)x0f, y0 = (int)y0f;

    const float* ip = img + (b * C + c) * HW;
    auto samp = [&](int yi, int xi) -> float {
        bool valid = (xi >= 0) && (xi < W) && (yi >= 0) && (yi < H);
        int yc = min(max(yi, 0), H - 1);
        int xc = min(max(xi, 0), W - 1);
        return valid ? ip[yc * W + xc] : 0.f;
    };
    float r = samp(y0,     x0    ) * (1.f - wx) * (1.f - wy)
            + samp(y0,     x0 + 1) * wx         * (1.f - wy)
            + samp(y0 + 1, x0    ) * (1.f - wx) * wy
            + samp(y0 + 1, x0 + 1) * wx         * wy;
    dst[((b * dstCtot) + dstCoff + c) * HW + p] = r;
}

// ---------------------------------------------------------------------------
__global__ void copy_strided_kernel(const float* __restrict__ src, float* __restrict__ dst,
                                    int perB, int srcStride, int dstStride, int B_)
{
    int i = blockIdx.x * blockDim.x + threadIdx.x;
    if (i >= B_ * perB) return;
    int b = i / perB, r = i - b * perB;
    dst[b * dstStride + r] = src[b * srcStride + r];
}

// ---------------------------------------------------------------------------
__global__ void upsample2x_kernel(const float* __restrict__ src, float* __restrict__ dst,
                                  int B_, int C, int Hi, int Wi)
{
    int Ho = Hi * 2, Wo = Wi * 2;
    int idx = blockIdx.x * blockDim.x + threadIdx.x;
    if (idx >= B_ * C * Ho * Wo) return;
    int wo = idx % Wo;
    int ho = (idx / Wo) % Ho;
    int bc = idx / (Wo * Ho);

    float sy = ho * 0.5f - 0.25f;
    float sx = wo * 0.5f - 0.25f;
    float fy = sy - floorf(sy);
    float fx = sx - floorf(sx);
    int y0 = (int)floorf(sy), x0 = (int)floorf(sx);
    int y0c = min(max(y0, 0), Hi - 1), y1c = min(max(y0 + 1, 0), Hi - 1);
    int x0c = min(max(x0, 0), Wi - 1), x1c = min(max(x0 + 1, 0), Wi - 1);

    const float* sp = src + bc * Hi * Wi;
    float v = sp[y0c * Wi + x0c] * (1.f - fy) * (1.f - fx)
            + sp[y0c * Wi + x1c] * (1.f - fy) * fx
            + sp[y1c * Wi + x0c] * fy * (1.f - fx)
            + sp[y1c * Wi + x1c] * fy * fx;
    dst[idx] = v;
}

// ---------------------------------------------------------------------------
__global__ void conv1x1_3_kernel(
    const float* __restrict__ x, const float* __restrict__ w5, const float* __restrict__ b5,
    const float* __restrict__ base, int baseC, int baseStrideB,
    float* __restrict__ out, int Cin, int HW, int B_)
{
    int idx = blockIdx.x * blockDim.x + threadIdx.x;
    if (idx >= B_ * HW) return;
    int b = idx / HW, p = idx - b * HW;

    float a0 = 0.f, a1 = 0.f, a2 = 0.f;
    const float* xp = x + (size_t)b * Cin * HW + p;
    for (int ci = 0; ci < Cin; ci++) {
        float v = xp[(size_t)ci * HW];
        a0 = fmaf(v, __ldg(&w5[ci]),            a0);
        a1 = fmaf(v, __ldg(&w5[Cin + ci]),      a1);
        a2 = fmaf(v, __ldg(&w5[2 * Cin + ci]),  a2);
    }
    float b0v = base[b * baseStrideB + p];
    float b1v = base[b * baseStrideB + HW + p];
    float b2v = (baseC > 2) ? base[b * baseStrideB + 2 * HW + p] : 0.f;

    out[(size_t)b * 3 * HW + p]           = a0 + __ldg(&b5[0]) + b0v;
    out[(size_t)b * 3 * HW + HW + p]      = a1 + __ldg(&b5[1]) + b1v;
    out[(size_t)b * 3 * HW + 2 * HW + p]  = a2 + __ldg(&b5[2]) + b2v;
}

// ---------------------------------------------------------------------------
extern "C" void kernel_launch(void* const* d_in, const int* in_sizes, int n_in,
                              void* d_out, int out_size)
{
    const float* f0c = (const float*)d_in[0];
    const float* f1c = (const float*)d_in[1];
    const float* f0f = (const float*)d_in[2];
    const float* f1f = (const float*)d_in[3];
    const float* cw1 = (const float*)d_in[4];
    const float* cw2 = (const float*)d_in[5];
    const float* cw3 = (const float*)d_in[6];
    const float* cw4 = (const float*)d_in[7];
    const float* cw5 = (const float*)d_in[8];
    const float* cb5 = (const float*)d_in[9];
    const float* fw1 = (const float*)d_in[10];
    const float* fw2 = (const float*)d_in[11];
    const float* fw3 = (const float*)d_in[12];
    const float* fw4 = (const float*)d_in[13];
    const float* fw5 = (const float*)d_in[14];
    const float* fb5 = (const float*)d_in[15];

    float *A, *Bb, *warp, *stats;
    cudaGetSymbolAddress((void**)&A,     g_bufA);
    cudaGetSymbolAddress((void**)&Bb,    g_bufB);
    cudaGetSymbolAddress((void**)&warp,  g_warp);
    cudaGetSymbolAddress((void**)&stats, g_stats);

    float* outC = (float*)d_out;                 // (4,3,64,64)
    float* outF = outC + 4 * 3 * 64 * 64;        // (4,3,128,128)

    const int HWc = 64 * 64, HWf = 128 * 128;

    // ---- coarse stage ----
    corr_kernel<<<512, 128>>>(f0c, f1c, warp);

    copy_strided_kernel<<<(4 * 64 * HWc + 255) / 256, 256>>>(
        f0c, A, 64 * HWc, 64 * HWc, 130 * HWc, 4);
    copy_strided_kernel<<<(4 * 2 * HWc + 255) / 256, 256>>>(
        warp, A + 128 * HWc, 2 * HWc, 2 * HWc, 130 * HWc, 4);
    gridsample_kernel<<<(4 * 64 * HWc + 255) / 256, 256>>>(
        f1c, warp, A, 4, 64, 64, 64, 2 * HWc, HWc, 130, 64);

    dim3 cg(1, 16, 32);   // W/64=1, H/4=16, B*Cout/32=32
    conv3x3_kernel<<<cg, 256>>>(A, cw1, nullptr, Bb, 4, 130, 256, 64, 64);
    bnstats_kernel<<<256, 512>>>(Bb, stats, 4, 256, HWc);

    conv3x3_kernel<<<cg, 256>>>(Bb, cw2, stats, A, 4, 256, 256, 64, 64);   // folds BN+relu of Bb
    bnstats_kernel<<<256, 512>>>(A, stats, 4, 256, HWc);

    conv3x3_kernel<<<cg, 256>>>(A, cw3, stats, Bb, 4, 256, 256, 64, 64);
    bnstats_kernel<<<256, 512>>>(Bb, stats, 4, 256, HWc);

    conv3x3_kernel<<<cg, 256>>>(Bb, cw4, stats, A, 4, 256, 256, 64, 64);
    bnstats_kernel<<<256, 512>>>(A, stats, 4, 256, HWc);
    bnrelu_kernel<<<(4 * 256 * HWc + 255) / 256, 256>>>(A, stats, 256, HWc, 4 * 256 * HWc);

    conv1x1_3_kernel<<<(4 * HWc + 127) / 128, 128>>>(
        A, cw5, cb5, warp, 2, 2 * HWc, outC, 256, HWc, 4);

    // ---- fine stage ----
    upsample2x_kernel<<<(4 * 3 * HWf + 255) / 256, 256>>>(outC, outF, 4, 3, 64, 64);

    copy_strided_kernel<<<(4 * 24 * HWf + 255) / 256, 256>>>(
        f0f, Bb, 24 * HWf, 24 * HWf, 50 * HWf, 4);
    copy_strided_kernel<<<(4 * 2 * HWf + 255) / 256, 256>>>(
        outF, Bb + 48 * HWf, 2 * HWf, 3 * HWf, 50 * HWf, 4);
    gridsample_kernel<<<(4 * 24 * HWf + 255) / 256, 256>>>(
        f1f, outF, Bb, 4, 24, 128, 128, 3 * HWf, HWf, 50, 24);

    dim3 fg(2, 32, 8);    // W/64=2, H/4=32, B*Cout/32=8
    conv3x3_kernel<<<fg, 256>>>(Bb, fw1, nullptr, A, 4, 50, 64, 128, 128);
    bnstats_kernel<<<64, 512>>>(A, stats, 4, 64, HWf);

    conv3x3_kernel<<<fg, 256>>>(A, fw2, stats, Bb, 4, 64, 64, 128, 128);
    bnstats_kernel<<<64, 512>>>(Bb, stats, 4, 64, HWf);

    conv3x3_kernel<<<fg, 256>>>(Bb, fw3, stats, A, 4, 64, 64, 128, 128);
    bnstats_kernel<<<64, 512>>>(A, stats, 4, 64, HWf);

    conv3x3_kernel<<<fg, 256>>>(A, fw4, stats, Bb, 4, 64, 64, 128, 128);
    bnstats_kernel<<<64, 512>>>(Bb, stats, 4, 64, HWf);
    bnrelu_kernel<<<(4 * 64 * HWf + 255) / 256, 256>>>(Bb, stats, 64, HWf, 4 * 64 * HWf);

    conv1x1_3_kernel<<<(4 * HWf + 127) / 128, 128>>>(
        Bb, fw5, fb5, outF, 3, 3 * HWf, outF, 64, HWf, 4);
}